// round 9
// baseline (speedup 1.0000x reference)
#include <cuda_runtime.h>
#include <math.h>

// Problem dims (x is batch_first [B, T, D]; B=32, T=1024)
#define BB 32
#define TT 1024
#define DD 256
#define HH 512
#define G4 2048   // 4*H
#define NCTA 128
#define BH (BB * HH)

// ---- scratch inside device globals (no allocations allowed) ----
#define OFF_XP   0u                                        // [T,B,4H]
#define OFF_HS0  (OFF_XP  + (size_t)TT * BB * G4)          // [T,B,H]
#define OFF_HBUF (OFF_HS0 + (size_t)TT * BB * HH)          // 2*[B,H] ping-pong
#define SCRATCH_SZ (OFF_HBUF + 2u * (size_t)BB * HH)

__device__ float    g_scratch[SCRATCH_SZ];
__device__ unsigned g_bar[TT];

// smem layout (floats): Wsm 16x516 | Hsm 32x516 | Psm 8*32*17
#define WSM_STRIDE 516
#define PSM_STRIDE 17
#define WSM_FLOATS (16 * WSM_STRIDE)
#define HSM_FLOATS (32 * WSM_STRIDE)
#define PSM_FLOATS (8 * 32 * PSM_STRIDE)
#define SMEM_BYTES ((WSM_FLOATS + HSM_FLOATS + PSM_FLOATS) * sizeof(float))

// ---------------------------------------------------------------------------
// Input projection GEMM: Y[m][n] = dot(X(m,:), W[n,:]) + bias[n], N = 2048.
// Logical row m = t*BB + b.
// MODE 0: X row-major [T*B, K].  MODE 1: X is x[B][T][D]; row m -> b*(T*D)+t*D.
// ---------------------------------------------------------------------------
template <int MODE, int K>
__global__ __launch_bounds__(256) void gemm_proj(const float* __restrict__ X,
                                                 const float* __restrict__ W,
                                                 const float* __restrict__ bias,
                                                 float* __restrict__ Y)
{
    __shared__ float Xs[16][64];
    __shared__ float Ws[16][64];

    const int n0  = blockIdx.x * 64;
    const int m0  = blockIdx.y * 64;
    const int tid = threadIdx.x;
    const int tx  = tid & 15;
    const int ty  = tid >> 4;
    const int lrow = tid >> 2;          // 0..63
    const int kp   = (tid & 3) * 4;     // 0,4,8,12

    const float* xrow;
    if (MODE == 0) {
        xrow = X + (size_t)(m0 + lrow) * K;
    } else {
        int m = m0 + lrow;
        int b = m & (BB - 1);
        int t = m >> 5;
        xrow = X + (size_t)b * (TT * DD) + (size_t)t * DD;
    }
    const float* wrow = W + (size_t)(n0 + lrow) * K;

    float acc[4][4];
#pragma unroll
    for (int i = 0; i < 4; i++)
#pragma unroll
        for (int j = 0; j < 4; j++) acc[i][j] = 0.f;

    for (int kk = 0; kk < K; kk += 16) {
        float4 xa = *(const float4*)(xrow + kk + kp);
        float4 wa = *(const float4*)(wrow + kk + kp);
        __syncthreads();
        Xs[kp + 0][lrow] = xa.x; Xs[kp + 1][lrow] = xa.y;
        Xs[kp + 2][lrow] = xa.z; Xs[kp + 3][lrow] = xa.w;
        Ws[kp + 0][lrow] = wa.x; Ws[kp + 1][lrow] = wa.y;
        Ws[kp + 2][lrow] = wa.z; Ws[kp + 3][lrow] = wa.w;
        __syncthreads();
#pragma unroll
        for (int k = 0; k < 16; k++) {
            float4 a = *(const float4*)&Xs[k][ty * 4];
            float4 b = *(const float4*)&Ws[k][tx * 4];
            float av[4] = {a.x, a.y, a.z, a.w};
            float bv[4] = {b.x, b.y, b.z, b.w};
#pragma unroll
            for (int i = 0; i < 4; i++)
#pragma unroll
                for (int j = 0; j < 4; j++) acc[i][j] += av[i] * bv[j];
        }
    }

#pragma unroll
    for (int i = 0; i < 4; i++) {
        int m = m0 + ty * 4 + i;
        float* yr = Y + (size_t)m * G4 + n0 + tx * 4;
#pragma unroll
        for (int j = 0; j < 4; j++)
            yr[j] = acc[i][j] + bias[n0 + tx * 4 + j];
    }
}

// ---------------------------------------------------------------------------
// Persistent recurrent kernel: one launch per layer, internal loop over T.
// 128 CTAs; CTA owns h-cols h0..h0+3 (16 gate rows). Whh slice cached in
// smem once; h staged to smem each step via L2 (__ldcg); c in registers.
// Grid-wide sync between steps via per-step counters (release/acquire).
// ---------------------------------------------------------------------------
__global__ __launch_bounds__(256) void lstm_seq(const float* __restrict__ Whh,
                                                const float* __restrict__ xp,
                                                float* __restrict__ hbuf,
                                                float* __restrict__ seq,
                                                long st_t, long st_b,
                                                float* __restrict__ hn,
                                                float* __restrict__ cn,
                                                unsigned* __restrict__ bar)
{
    extern __shared__ float sm[];
    float* Wsm = sm;
    float* Hsm = sm + WSM_FLOATS;
    float* Psm = sm + WSM_FLOATS + HSM_FLOATS;

    const int tid = threadIdx.x;
    const int h0  = blockIdx.x * 4;

    // ---- load Whh slice once: row r = g*4 + j  ->  Whh[(g*H + h0 + j)*H + k]
    {
        int r  = tid >> 4;             // 0..15
        int k0 = (tid & 15) * 32;      // 16 threads per row, 32 floats each
        const float* grow = Whh + (size_t)((r >> 2) * HH + h0 + (r & 3)) * HH + k0;
#pragma unroll
        for (int q = 0; q < 32; q += 4)
            *(float4*)&Wsm[r * WSM_STRIDE + k0 + q] = *(const float4*)(grow + q);
    }

    const int kz = tid >> 5;           // k-slice of 64
    const int w  = tid & 31;
    const int bt = w >> 2;             // batch group (4 batches)
    const int nt = w & 3;              // gate
    const int ub = tid >> 2;           // update: batch
    const int uj = tid & 3;            // update: h-col offset

    float cv = 0.f;                    // cell state lives in a register

    for (int t = 0; t < TT; ++t) {
        const float* hprev = hbuf + (size_t)(t & 1) * BH;
        float*       hnext = hbuf + (size_t)((t + 1) & 1) * BH;
        const float* xp_t  = xp + (size_t)t * BB * G4;

        // prefetch gate biases (consumed after the GEMM)
        float xpv[4];
        if (tid < 128) {
#pragma unroll
            for (int g = 0; g < 4; g++)
                xpv[g] = __ldg(xp_t + (size_t)ub * G4 + g * HH + h0 + uj);
        }

        // stage h -> smem (L2-coherent reads)
        {
            int b  = tid >> 3;         // 0..31
            int k0 = (tid & 7) * 64;   // 8 threads per batch row
#pragma unroll
            for (int q = 0; q < 64; q += 4) {
                float4 v = __ldcg((const float4*)(hprev + (size_t)b * HH + k0 + q));
                *(float4*)&Hsm[b * WSM_STRIDE + k0 + q] = v;
            }
        }
        __syncthreads();

        // GEMM: 4 batches x 4 gate-rows over 64-k slice
        float acc[4][4];
#pragma unroll
        for (int i = 0; i < 4; i++)
#pragma unroll
            for (int j = 0; j < 4; j++) acc[i][j] = 0.f;

        const float* hbase = &Hsm[(bt * 4) * WSM_STRIDE + kz * 64];
        const float* wbase = &Wsm[(nt * 4) * WSM_STRIDE + kz * 64];
#pragma unroll
        for (int kk = 0; kk < 64; kk += 4) {
            float4 hv[4], wv[4];
#pragma unroll
            for (int i = 0; i < 4; i++)
                hv[i] = *(const float4*)(hbase + i * WSM_STRIDE + kk);
#pragma unroll
            for (int j = 0; j < 4; j++)
                wv[j] = *(const float4*)(wbase + j * WSM_STRIDE + kk);
#pragma unroll
            for (int i = 0; i < 4; i++)
#pragma unroll
                for (int j = 0; j < 4; j++)
                    acc[i][j] += hv[i].x * wv[j].x + hv[i].y * wv[j].y
                               + hv[i].z * wv[j].z + hv[i].w * wv[j].w;
        }

#pragma unroll
        for (int i = 0; i < 4; i++)
#pragma unroll
            for (int j = 0; j < 4; j++)
                Psm[(kz * 32 + w) * PSM_STRIDE + i * 4 + j] = acc[i][j];
        __syncthreads();

        // elementwise update (128 threads: batch ub, h-col h0+uj)
        if (tid < 128) {
            float gate[4];
#pragma unroll
            for (int g = 0; g < 4; g++) {
                float s = xpv[g];
#pragma unroll
                for (int z = 0; z < 8; z++)
                    s += Psm[(z * 32 + (ub >> 2) * 4 + g) * PSM_STRIDE + (ub & 3) * 4 + uj];
                gate[g] = s;
            }
            float iv = 1.f / (1.f + expf(-gate[0]));
            float fv = 1.f / (1.f + expf(-gate[1]));
            float gv = tanhf(gate[2]);
            float ov = 1.f / (1.f + expf(-gate[3]));
            cv = fv * cv + iv * gv;
            float hv = ov * tanhf(cv);
            __stcg(hnext + (size_t)ub * HH + h0 + uj, hv);
            seq[(size_t)t * st_t + (size_t)ub * st_b + h0 + uj] = hv;
            if (t == TT - 1 && hn) {
                hn[ub * HH + h0 + uj] = hv;
                cn[ub * HH + h0 + uj] = cv;
            }
            __threadfence();
        }
        __syncthreads();

        // grid barrier (per-step counter; zeroed by a memset node pre-launch)
        if (tid == 0) {
            unsigned* p = &bar[t];
            unsigned one = 1u;
            asm volatile("red.release.gpu.global.add.u32 [%0], %1;"
                         :: "l"(p), "r"(one) : "memory");
            unsigned v;
            do {
                asm volatile("ld.acquire.gpu.global.u32 %0, [%1];"
                             : "=r"(v) : "l"(p) : "memory");
            } while (v < (unsigned)NCTA);
        }
        __syncthreads();
    }
}

// ---------------------------------------------------------------------------
extern "C" void kernel_launch(void* const* d_in, const int* in_sizes, int n_in,
                              void* d_out, int out_size)
{
    const float* x    = (const float*)d_in[0];
    const float* Wih0 = (const float*)d_in[1];
    const float* b0   = (const float*)d_in[2];
    const float* Whh0 = (const float*)d_in[3];
    const float* Wih1 = (const float*)d_in[4];
    const float* b1   = (const float*)d_in[5];
    const float* Whh1 = (const float*)d_in[6];
    float* out = (float*)d_out;

    float* scratch = nullptr;
    unsigned* bar = nullptr;
    cudaGetSymbolAddress((void**)&scratch, g_scratch);
    cudaGetSymbolAddress((void**)&bar, g_bar);
    float* xp   = scratch + OFF_XP;
    float* hs0  = scratch + OFF_HS0;
    float* hbuf = scratch + OFF_HBUF;

    cudaFuncSetAttribute(lstm_seq, cudaFuncAttributeMaxDynamicSharedMemorySize,
                         (int)SMEM_BYTES);

    // outputs: output[B,T,H] ++ h_n[2,B,H] ++ c_n[2,B,H]
    const size_t main_sz = (size_t)BB * TT * HH;            // 16,777,216
    const size_t full_sz = main_sz + 4u * (size_t)BH;       // 16,842,752
    const bool   tail_ok = ((size_t)out_size >= full_sz);
    float* hn_base = tail_ok ? out + main_sz : nullptr;
    float* cn_base = tail_ok ? out + main_sz + 2u * (size_t)BH : nullptr;

    dim3 gproj(G4 / 64, (TT * BB) / 64);  // (32, 512)

    // ---- layer 0 ----
    gemm_proj<1, DD><<<gproj, 256>>>(x, Wih0, b0, xp);
    cudaMemsetAsync(hbuf, 0, 2u * (size_t)BH * sizeof(float));
    cudaMemsetAsync(bar, 0, TT * sizeof(unsigned));
    lstm_seq<<<NCTA, 256, SMEM_BYTES>>>(Whh0, xp, hbuf,
                                        hs0, (long)BH, (long)HH,
                                        hn_base, cn_base, bar);

    // ---- layer 1 ----
    gemm_proj<0, HH><<<gproj, 256>>>(hs0, Wih1, b1, xp);
    cudaMemsetAsync(hbuf, 0, 2u * (size_t)BH * sizeof(float));
    cudaMemsetAsync(bar, 0, TT * sizeof(unsigned));
    lstm_seq<<<NCTA, 256, SMEM_BYTES>>>(Whh1, xp, hbuf,
                                        out, (long)HH, (long)(TT * HH),
                                        hn_base ? hn_base + BH : nullptr,
                                        cn_base ? cn_base + BH : nullptr, bar);
}

// round 11
// speedup vs baseline: 1.0033x; 1.0033x over previous
#include <cuda_runtime.h>
#include <math.h>

// Problem dims (x is batch_first [B, T, D]; B=32, T=1024)
#define BB 32
#define TT 1024
#define DD 256
#define HH 512
#define G4 2048   // 4*H
#define NCTA 128
#define BH (BB * HH)

// ---- scratch inside device globals (no allocations allowed) ----
#define OFF_XP   0u                                        // [T,B,4H]
#define OFF_HS0  (OFF_XP  + (size_t)TT * BB * G4)          // [T,B,H]
#define OFF_HBUF (OFF_HS0 + (size_t)TT * BB * HH)          // 2*[B,H] ping-pong
#define SCRATCH_SZ (OFF_HBUF + 2u * (size_t)BB * HH)

__device__ float    g_scratch[SCRATCH_SZ];
__device__ unsigned g_bar[TT];

// smem layout (floats): Wsm 16x516 | Hsm 32x516 | Psm 8*32*17
#define WSM_STRIDE 516
#define PSM_STRIDE 17
#define WSM_FLOATS (16 * WSM_STRIDE)
#define HSM_FLOATS (32 * WSM_STRIDE)
#define PSM_FLOATS (8 * 32 * PSM_STRIDE)
#define SMEM_BYTES ((WSM_FLOATS + HSM_FLOATS + PSM_FLOATS) * sizeof(float))

// ---------------------------------------------------------------------------
// Input projection GEMM: Y[m][n] = dot(X(m,:), W[n,:]) + bias[n], N = 2048.
// Logical row m = t*BB + b.
// MODE 0: X row-major [T*B, K].  MODE 1: X is x[B][T][D]; row m -> b*(T*D)+t*D.
// ---------------------------------------------------------------------------
template <int MODE, int K>
__global__ __launch_bounds__(256) void gemm_proj(const float* __restrict__ X,
                                                 const float* __restrict__ W,
                                                 const float* __restrict__ bias,
                                                 float* __restrict__ Y)
{
    __shared__ float Xs[16][64];
    __shared__ float Ws[16][64];

    const int n0  = blockIdx.x * 64;
    const int m0  = blockIdx.y * 64;
    const int tid = threadIdx.x;
    const int tx  = tid & 15;
    const int ty  = tid >> 4;
    const int lrow = tid >> 2;          // 0..63
    const int kp   = (tid & 3) * 4;     // 0,4,8,12

    const float* xrow;
    if (MODE == 0) {
        xrow = X + (size_t)(m0 + lrow) * K;
    } else {
        int m = m0 + lrow;
        int b = m & (BB - 1);
        int t = m >> 5;
        xrow = X + (size_t)b * (TT * DD) + (size_t)t * DD;
    }
    const float* wrow = W + (size_t)(n0 + lrow) * K;

    float acc[4][4];
#pragma unroll
    for (int i = 0; i < 4; i++)
#pragma unroll
        for (int j = 0; j < 4; j++) acc[i][j] = 0.f;

    for (int kk = 0; kk < K; kk += 16) {
        float4 xa = *(const float4*)(xrow + kk + kp);
        float4 wa = *(const float4*)(wrow + kk + kp);
        __syncthreads();
        Xs[kp + 0][lrow] = xa.x; Xs[kp + 1][lrow] = xa.y;
        Xs[kp + 2][lrow] = xa.z; Xs[kp + 3][lrow] = xa.w;
        Ws[kp + 0][lrow] = wa.x; Ws[kp + 1][lrow] = wa.y;
        Ws[kp + 2][lrow] = wa.z; Ws[kp + 3][lrow] = wa.w;
        __syncthreads();
#pragma unroll
        for (int k = 0; k < 16; k++) {
            float4 a = *(const float4*)&Xs[k][ty * 4];
            float4 b = *(const float4*)&Ws[k][tx * 4];
            float av[4] = {a.x, a.y, a.z, a.w};
            float bv[4] = {b.x, b.y, b.z, b.w};
#pragma unroll
            for (int i = 0; i < 4; i++)
#pragma unroll
                for (int j = 0; j < 4; j++) acc[i][j] += av[i] * bv[j];
        }
    }

#pragma unroll
    for (int i = 0; i < 4; i++) {
        int m = m0 + ty * 4 + i;
        float* yr = Y + (size_t)m * G4 + n0 + tx * 4;
#pragma unroll
        for (int j = 0; j < 4; j++)
            yr[j] = acc[i][j] + bias[n0 + tx * 4 + j];
    }
}

// ---------------------------------------------------------------------------
// Persistent recurrent kernel: one launch per layer, internal loop over T.
// 128 CTAs; CTA owns h-cols h0..h0+3 (16 gate rows). Whh slice in smem once;
// h staged to smem each step via L2 (__ldcg); c in registers.
// Grid sync = cooperative-groups pattern: bar.sync -> tid0 {fence.acq_rel.gpu,
// red.release.add, acquire-poll} -> bar.sync.  (NO per-thread membars.)
// ---------------------------------------------------------------------------
__global__ __launch_bounds__(256) void lstm_seq(const float* __restrict__ Whh,
                                                const float* __restrict__ xp,
                                                float* __restrict__ hbuf,
                                                float* __restrict__ seq,
                                                long st_t, long st_b,
                                                float* __restrict__ hn,
                                                float* __restrict__ cn,
                                                unsigned* __restrict__ bar)
{
    extern __shared__ float sm[];
    float* Wsm = sm;
    float* Hsm = sm + WSM_FLOATS;
    float* Psm = sm + WSM_FLOATS + HSM_FLOATS;

    const int tid = threadIdx.x;
    const int h0  = blockIdx.x * 4;

    // ---- load Whh slice once: row r = g*4 + j  ->  Whh[(g*H + h0 + j)*H + k]
    {
        int r  = tid >> 4;             // 0..15
        int k0 = (tid & 15) * 32;      // 16 threads per row, 32 floats each
        const float* grow = Whh + (size_t)((r >> 2) * HH + h0 + (r & 3)) * HH + k0;
#pragma unroll
        for (int q = 0; q < 32; q += 4)
            *(float4*)&Wsm[r * WSM_STRIDE + k0 + q] = *(const float4*)(grow + q);
    }

    const int kz = tid >> 5;           // k-slice of 64
    const int w  = tid & 31;
    const int bt = w >> 2;             // batch group (4 batches)
    const int nt = w & 3;              // gate
    const int ub = tid >> 2;           // update: batch
    const int uj = tid & 3;            // update: h-col offset

    float cv = 0.f;                    // cell state lives in a register

    for (int t = 0; t < TT; ++t) {
        const float* hprev = hbuf + (size_t)(t & 1) * BH;
        float*       hnext = hbuf + (size_t)((t + 1) & 1) * BH;
        const float* xp_t  = xp + (size_t)t * BB * G4;

        // prefetch gate biases (consumed after the GEMM)
        float xpv[4];
        if (tid < 128) {
#pragma unroll
            for (int g = 0; g < 4; g++)
                xpv[g] = __ldg(xp_t + (size_t)ub * G4 + g * HH + h0 + uj);
        }

        // stage h -> smem (L2-coherent reads)
        {
            int b  = tid >> 3;         // 0..31
            int k0 = (tid & 7) * 64;   // 8 threads per batch row
#pragma unroll
            for (int q = 0; q < 64; q += 4) {
                float4 v = __ldcg((const float4*)(hprev + (size_t)b * HH + k0 + q));
                *(float4*)&Hsm[b * WSM_STRIDE + k0 + q] = v;
            }
        }
        __syncthreads();

        // GEMM: 4 batches x 4 gate-rows over 64-k slice
        float acc[4][4];
#pragma unroll
        for (int i = 0; i < 4; i++)
#pragma unroll
            for (int j = 0; j < 4; j++) acc[i][j] = 0.f;

        const float* hbase = &Hsm[(bt * 4) * WSM_STRIDE + kz * 64];
        const float* wbase = &Wsm[(nt * 4) * WSM_STRIDE + kz * 64];
#pragma unroll
        for (int kk = 0; kk < 64; kk += 4) {
            float4 hv[4], wv[4];
#pragma unroll
            for (int i = 0; i < 4; i++)
                hv[i] = *(const float4*)(hbase + i * WSM_STRIDE + kk);
#pragma unroll
            for (int j = 0; j < 4; j++)
                wv[j] = *(const float4*)(wbase + j * WSM_STRIDE + kk);
#pragma unroll
            for (int i = 0; i < 4; i++)
#pragma unroll
                for (int j = 0; j < 4; j++)
                    acc[i][j] += hv[i].x * wv[j].x + hv[i].y * wv[j].y
                               + hv[i].z * wv[j].z + hv[i].w * wv[j].w;
        }

#pragma unroll
        for (int i = 0; i < 4; i++)
#pragma unroll
            for (int j = 0; j < 4; j++)
                Psm[(kz * 32 + w) * PSM_STRIDE + i * 4 + j] = acc[i][j];
        __syncthreads();

        // elementwise update (128 threads: batch ub, h-col h0+uj)
        if (tid < 128) {
            float gate[4];
#pragma unroll
            for (int g = 0; g < 4; g++) {
                float s = xpv[g];
#pragma unroll
                for (int z = 0; z < 8; z++)
                    s += Psm[(z * 32 + (ub >> 2) * 4 + g) * PSM_STRIDE + (ub & 3) * 4 + uj];
                gate[g] = s;
            }
            float iv = 1.f / (1.f + __expf(-gate[0]));
            float fv = 1.f / (1.f + __expf(-gate[1]));
            float gv = tanhf(gate[2]);
            float ov = 1.f / (1.f + __expf(-gate[3]));
            cv = fv * cv + iv * gv;
            float hv = ov * tanhf(cv);
            __stcg(hnext + (size_t)ub * HH + h0 + uj, hv);
            seq[(size_t)t * st_t + (size_t)ub * st_b + h0 + uj] = hv;
            if (t == TT - 1 && hn) {
                hn[ub * HH + h0 + uj] = hv;
                cn[ub * HH + h0 + uj] = cv;
            }
        }
        __syncthreads();   // all h stores issued before the fence below

        // grid barrier (cooperative-groups pattern; counters zeroed pre-launch)
        if (tid == 0) {
            unsigned* p = &bar[t];
            unsigned one = 1u;
            asm volatile("fence.acq_rel.gpu;" ::: "memory");
            asm volatile("red.release.gpu.global.add.u32 [%0], %1;"
                         :: "l"(p), "r"(one) : "memory");
            unsigned v;
            do {
                asm volatile("ld.acquire.gpu.global.u32 %0, [%1];"
                             : "=r"(v) : "l"(p) : "memory");
            } while (v < (unsigned)NCTA);
        }
        __syncthreads();
    }
}

// ---------------------------------------------------------------------------
extern "C" void kernel_launch(void* const* d_in, const int* in_sizes, int n_in,
                              void* d_out, int out_size)
{
    const float* x    = (const float*)d_in[0];
    const float* Wih0 = (const float*)d_in[1];
    const float* b0   = (const float*)d_in[2];
    const float* Whh0 = (const float*)d_in[3];
    const float* Wih1 = (const float*)d_in[4];
    const float* b1   = (const float*)d_in[5];
    const float* Whh1 = (const float*)d_in[6];
    float* out = (float*)d_out;

    float* scratch = nullptr;
    unsigned* bar = nullptr;
    cudaGetSymbolAddress((void**)&scratch, g_scratch);
    cudaGetSymbolAddress((void**)&bar, g_bar);
    float* xp   = scratch + OFF_XP;
    float* hs0  = scratch + OFF_HS0;
    float* hbuf = scratch + OFF_HBUF;

    cudaFuncSetAttribute(lstm_seq, cudaFuncAttributeMaxDynamicSharedMemorySize,
                         (int)SMEM_BYTES);

    // outputs: output[B,T,H] ++ h_n[2,B,H] ++ c_n[2,B,H]
    const size_t main_sz = (size_t)BB * TT * HH;            // 16,777,216
    const size_t full_sz = main_sz + 4u * (size_t)BH;       // 16,842,752
    const bool   tail_ok = ((size_t)out_size >= full_sz);
    float* hn_base = tail_ok ? out + main_sz : nullptr;
    float* cn_base = tail_ok ? out + main_sz + 2u * (size_t)BH : nullptr;

    dim3 gproj(G4 / 64, (TT * BB) / 64);  // (32, 512)

    // ---- layer 0 ----
    gemm_proj<1, DD><<<gproj, 256>>>(x, Wih0, b0, xp);
    cudaMemsetAsync(hbuf, 0, 2u * (size_t)BH * sizeof(float));
    cudaMemsetAsync(bar, 0, TT * sizeof(unsigned));
    lstm_seq<<<NCTA, 256, SMEM_BYTES>>>(Whh0, xp, hbuf,
                                        hs0, (long)BH, (long)HH,
                                        hn_base, cn_base, bar);

    // ---- layer 1 ----
    gemm_proj<0, HH><<<gproj, 256>>>(hs0, Wih1, b1, xp);
    cudaMemsetAsync(hbuf, 0, 2u * (size_t)BH * sizeof(float));
    cudaMemsetAsync(bar, 0, TT * sizeof(unsigned));
    lstm_seq<<<NCTA, 256, SMEM_BYTES>>>(Whh1, xp, hbuf,
                                        out, (long)HH, (long)(TT * HH),
                                        hn_base ? hn_base + BH : nullptr,
                                        cn_base ? cn_base + BH : nullptr, bar);
}

// round 13
// speedup vs baseline: 2.7084x; 2.6995x over previous
#include <cuda_runtime.h>
#include <math.h>

// Problem dims (x is batch_first [B, T, D]; B=32, T=1024)
#define BB 32
#define TT 1024
#define DD 256
#define HH 512
#define G4 2048   // 4*H
#define NCTA 128
#define BH (BB * HH)

// ---- scratch inside device globals (no allocations allowed) ----
#define OFF_XP   0u                                        // [T,B,4H]
#define OFF_HS0  (OFF_XP  + (size_t)TT * BB * G4)          // [T,B,H]
#define OFF_HBUF (OFF_HS0 + (size_t)TT * BB * HH)          // 2*[B,H] ping-pong
#define SCRATCH_SZ (OFF_HBUF + 2u * (size_t)BB * HH)

__device__ float    g_scratch[SCRATCH_SZ];
__device__ unsigned g_bar[TT];

// smem layout (floats): Wsm 16x516 | Hsm 32x516 | Psm 8*32*17
#define WSM_STRIDE 516
#define PSM_STRIDE 17
#define WSM_FLOATS (16 * WSM_STRIDE)
#define HSM_FLOATS (32 * WSM_STRIDE)
#define PSM_FLOATS (8 * 32 * PSM_STRIDE)
#define SMEM_BYTES ((WSM_FLOATS + HSM_FLOATS + PSM_FLOATS) * sizeof(float))

__device__ __forceinline__ float fast_tanh(float x) {
    float y;
    asm("tanh.approx.f32 %0, %1;" : "=f"(y) : "f"(x));
    return y;
}
__device__ __forceinline__ float fast_sigmoid(float x) {
    return 0.5f * fast_tanh(0.5f * x) + 0.5f;
}

// ---------------------------------------------------------------------------
// Input projection GEMM: Y[m][n] = dot(X(m,:), W[n,:]) + bias[n], N = 2048.
// Logical row m = t*BB + b.
// MODE 0: X row-major [T*B, K].  MODE 1: X is x[B][T][D]; row m -> b*(T*D)+t*D.
// ---------------------------------------------------------------------------
template <int MODE, int K>
__global__ __launch_bounds__(256) void gemm_proj(const float* __restrict__ X,
                                                 const float* __restrict__ W,
                                                 const float* __restrict__ bias,
                                                 float* __restrict__ Y)
{
    __shared__ float Xs[16][64];
    __shared__ float Ws[16][64];

    const int n0  = blockIdx.x * 64;
    const int m0  = blockIdx.y * 64;
    const int tid = threadIdx.x;
    const int tx  = tid & 15;
    const int ty  = tid >> 4;
    const int lrow = tid >> 2;          // 0..63
    const int kp   = (tid & 3) * 4;     // 0,4,8,12

    const float* xrow;
    if (MODE == 0) {
        xrow = X + (size_t)(m0 + lrow) * K;
    } else {
        int m = m0 + lrow;
        int b = m & (BB - 1);
        int t = m >> 5;
        xrow = X + (size_t)b * (TT * DD) + (size_t)t * DD;
    }
    const float* wrow = W + (size_t)(n0 + lrow) * K;

    float acc[4][4];
#pragma unroll
    for (int i = 0; i < 4; i++)
#pragma unroll
        for (int j = 0; j < 4; j++) acc[i][j] = 0.f;

    for (int kk = 0; kk < K; kk += 16) {
        float4 xa = *(const float4*)(xrow + kk + kp);
        float4 wa = *(const float4*)(wrow + kk + kp);
        __syncthreads();
        Xs[kp + 0][lrow] = xa.x; Xs[kp + 1][lrow] = xa.y;
        Xs[kp + 2][lrow] = xa.z; Xs[kp + 3][lrow] = xa.w;
        Ws[kp + 0][lrow] = wa.x; Ws[kp + 1][lrow] = wa.y;
        Ws[kp + 2][lrow] = wa.z; Ws[kp + 3][lrow] = wa.w;
        __syncthreads();
#pragma unroll
        for (int k = 0; k < 16; k++) {
            float4 a = *(const float4*)&Xs[k][ty * 4];
            float4 b = *(const float4*)&Ws[k][tx * 4];
            float av[4] = {a.x, a.y, a.z, a.w};
            float bv[4] = {b.x, b.y, b.z, b.w};
#pragma unroll
            for (int i = 0; i < 4; i++)
#pragma unroll
                for (int j = 0; j < 4; j++) acc[i][j] += av[i] * bv[j];
        }
    }

#pragma unroll
    for (int i = 0; i < 4; i++) {
        int m = m0 + ty * 4 + i;
        float* yr = Y + (size_t)m * G4 + n0 + tx * 4;
#pragma unroll
        for (int j = 0; j < 4; j++)
            yr[j] = acc[i][j] + bias[n0 + tx * 4 + j];
    }
}

// ---------------------------------------------------------------------------
// Persistent recurrent kernel: one launch per layer, internal loop over T.
// 128 CTAs; CTA owns h-cols h0..h0+3 (16 gate rows). Whh slice in smem once;
// h staged to smem each step (coalesced); c in registers.
// GEMM tile: thread (kz, bt, nt) computes batches {bt+8i} x gate-rows {nt+4j}
// over its 64-k slice -> Hsm lane-group stride is 1 row (banks 4*bt, all
// distinct) and Wsm lane-group stride 1 row (banks 4*nt, distinct): no LDS
// bank conflicts.  acc[i][j] = partial(batch bt+8i, gate j, hcol nt).
// ---------------------------------------------------------------------------
__global__ __launch_bounds__(256) void lstm_seq(const float* __restrict__ Whh,
                                                const float* __restrict__ xp,
                                                float* __restrict__ hbuf,
                                                float* __restrict__ seq,
                                                long st_t, long st_b,
                                                float* __restrict__ hn,
                                                float* __restrict__ cn,
                                                unsigned* __restrict__ bar)
{
    extern __shared__ float sm[];
    float* Wsm = sm;
    float* Hsm = sm + WSM_FLOATS;
    float* Psm = sm + WSM_FLOATS + HSM_FLOATS;

    const int tid = threadIdx.x;
    const int h0  = blockIdx.x * 4;

    // ---- load Whh slice once (coalesced flat float4):
    // Wsm row r (0..15) <-> gate r>>2, h-col r&3 :  Whh[((r>>2)*H + h0 + (r&3))*H + k]
#pragma unroll
    for (int it = 0; it < 8; it++) {
        int flat = it * 256 + tid;          // float4 index, 2048 total
        int r    = flat >> 7;               // 128 float4 per row
        int cc   = (flat & 127) * 4;
        const float* grow = Whh + (size_t)((r >> 2) * HH + h0 + (r & 3)) * HH;
        *(float4*)&Wsm[r * WSM_STRIDE + cc] = *(const float4*)(grow + cc);
    }

    const int kz = tid >> 5;           // k-slice of 64
    const int w  = tid & 31;
    const int bt = w >> 2;             // batch lane-group (owns batches bt+8i)
    const int nt = w & 3;              // gate-row lane-group (owns rows nt+4j)
    const int ub = tid >> 2;           // update: batch
    const int uj = tid & 3;            // update: h-col offset

    float cv = 0.f;                    // cell state lives in a register

    for (int t = 0; t < TT; ++t) {
        const float* hprev = hbuf + (size_t)(t & 1) * BH;
        float*       hnext = hbuf + (size_t)((t + 1) & 1) * BH;
        const float* xp_t  = xp + (size_t)t * BB * G4;

        // prefetch gate biases (consumed after the GEMM)
        float xpv[4];
        if (tid < 128) {
#pragma unroll
            for (int g = 0; g < 4; g++)
                xpv[g] = __ldg(xp_t + (size_t)ub * G4 + g * HH + h0 + uj);
        }

        // stage h -> smem, coalesced: consecutive lanes read consecutive 16B
#pragma unroll
        for (int it = 0; it < 16; it++) {
            int flat = it * 256 + tid;      // float4 index, 4096 total
            int b    = flat >> 7;
            int cc   = (flat & 127) * 4;
            float4 v = __ldcg((const float4*)(hprev + (size_t)b * HH + cc));
            *(float4*)&Hsm[b * WSM_STRIDE + cc] = v;
        }
        __syncthreads();

        // GEMM: 4 batches (bt+8i) x 4 gate-rows (nt+4j) over 64-k slice
        float acc[4][4];
#pragma unroll
        for (int i = 0; i < 4; i++)
#pragma unroll
            for (int j = 0; j < 4; j++) acc[i][j] = 0.f;

        const float* hbase = &Hsm[bt * WSM_STRIDE + kz * 64];
        const float* wbase = &Wsm[nt * WSM_STRIDE + kz * 64];
#pragma unroll
        for (int kk = 0; kk < 64; kk += 4) {
            float4 hv[4], wv[4];
#pragma unroll
            for (int i = 0; i < 4; i++)
                hv[i] = *(const float4*)(hbase + i * 8 * WSM_STRIDE + kk);
#pragma unroll
            for (int j = 0; j < 4; j++)
                wv[j] = *(const float4*)(wbase + j * 4 * WSM_STRIDE + kk);
#pragma unroll
            for (int i = 0; i < 4; i++)
#pragma unroll
                for (int j = 0; j < 4; j++)
                    acc[i][j] += hv[i].x * wv[j].x + hv[i].y * wv[j].y
                               + hv[i].z * wv[j].z + hv[i].w * wv[j].w;
        }

#pragma unroll
        for (int i = 0; i < 4; i++)
#pragma unroll
            for (int j = 0; j < 4; j++)
                Psm[(kz * 32 + w) * PSM_STRIDE + i * 4 + j] = acc[i][j];
        __syncthreads();

        // elementwise update (128 threads: batch ub, h-col h0+uj)
        // partial(batch B, gate g, hcol J) lives at producer lane (B&7)*4+J,
        // element (B>>3)*4+g
        if (tid < 128) {
            float gate[4];
#pragma unroll
            for (int g = 0; g < 4; g++) {
                float s = xpv[g];
#pragma unroll
                for (int z = 0; z < 8; z++)
                    s += Psm[(z * 32 + (ub & 7) * 4 + uj) * PSM_STRIDE + (ub >> 3) * 4 + g];
                gate[g] = s;
            }
            float iv = fast_sigmoid(gate[0]);
            float fv = fast_sigmoid(gate[1]);
            float gv = fast_tanh(gate[2]);
            float ov = fast_sigmoid(gate[3]);
            cv = fv * cv + iv * gv;
            float hv = ov * fast_tanh(cv);
            __stcg(hnext + (size_t)ub * HH + h0 + uj, hv);
            seq[(size_t)t * st_t + (size_t)ub * st_b + h0 + uj] = hv;
            if (t == TT - 1 && hn) {
                hn[ub * HH + h0 + uj] = hv;
                cn[ub * HH + h0 + uj] = cv;
            }
        }
        __syncthreads();   // all h stores issued before the fence below

        // grid barrier (cooperative-groups pattern; counters zeroed pre-launch)
        if (tid == 0) {
            unsigned* p = &bar[t];
            unsigned one = 1u;
            asm volatile("fence.acq_rel.gpu;" ::: "memory");
            asm volatile("red.release.gpu.global.add.u32 [%0], %1;"
                         :: "l"(p), "r"(one) : "memory");
            unsigned v;
            do {
                asm volatile("ld.acquire.gpu.global.u32 %0, [%1];"
                             : "=r"(v) : "l"(p) : "memory");
            } while (v < (unsigned)NCTA);
        }
        __syncthreads();
    }
}

// ---------------------------------------------------------------------------
extern "C" void kernel_launch(void* const* d_in, const int* in_sizes, int n_in,
                              void* d_out, int out_size)
{
    const float* x    = (const float*)d_in[0];
    const float* Wih0 = (const float*)d_in[1];
    const float* b0   = (const float*)d_in[2];
    const float* Whh0 = (const float*)d_in[3];
    const float* Wih1 = (const float*)d_in[4];
    const float* b1   = (const float*)d_in[5];
    const float* Whh1 = (const float*)d_in[6];
    float* out = (float*)d_out;

    float* scratch = nullptr;
    unsigned* bar = nullptr;
    cudaGetSymbolAddress((void**)&scratch, g_scratch);
    cudaGetSymbolAddress((void**)&bar, g_bar);
    float* xp   = scratch + OFF_XP;
    float* hs0  = scratch + OFF_HS0;
    float* hbuf = scratch + OFF_HBUF;

    cudaFuncSetAttribute(lstm_seq, cudaFuncAttributeMaxDynamicSharedMemorySize,
                         (int)SMEM_BYTES);

    // outputs: output[B,T,H] ++ h_n[2,B,H] ++ c_n[2,B,H]
    const size_t main_sz = (size_t)BB * TT * HH;            // 16,777,216
    const size_t full_sz = main_sz + 4u * (size_t)BH;       // 16,842,752
    const bool   tail_ok = ((size_t)out_size >= full_sz);
    float* hn_base = tail_ok ? out + main_sz : nullptr;
    float* cn_base = tail_ok ? out + main_sz + 2u * (size_t)BH : nullptr;

    dim3 gproj(G4 / 64, (TT * BB) / 64);  // (32, 512)

    // ---- layer 0 ----
    gemm_proj<1, DD><<<gproj, 256>>>(x, Wih0, b0, xp);
    cudaMemsetAsync(hbuf, 0, 2u * (size_t)BH * sizeof(float));
    cudaMemsetAsync(bar, 0, TT * sizeof(unsigned));
    lstm_seq<<<NCTA, 256, SMEM_BYTES>>>(Whh0, xp, hbuf,
                                        hs0, (long)BH, (long)HH,
                                        hn_base, cn_base, bar);

    // ---- layer 1 ----
    gemm_proj<0, HH><<<gproj, 256>>>(hs0, Wih1, b1, xp);
    cudaMemsetAsync(hbuf, 0, 2u * (size_t)BH * sizeof(float));
    cudaMemsetAsync(bar, 0, TT * sizeof(unsigned));
    lstm_seq<<<NCTA, 256, SMEM_BYTES>>>(Whh1, xp, hbuf,
                                        out, (long)HH, (long)(TT * HH),
                                        hn_base ? hn_base + BH : nullptr,
                                        cn_base ? cn_base + BH : nullptr, bar);
}

// round 14
// speedup vs baseline: 2.7820x; 1.0272x over previous
#include <cuda_runtime.h>
#include <math.h>

// Problem dims (x is batch_first [B, T, D]; B=32, T=1024)
#define BB 32
#define TT 1024
#define DD 256
#define HH 512
#define G4 2048   // 4*H
#define NCTA 128
#define BH (BB * HH)

// ---- scratch inside device globals (no allocations allowed) ----
#define OFF_XP   0u                                        // [T,B,4H]
#define OFF_HS0  (OFF_XP  + (size_t)TT * BB * G4)          // [T,B,H]
#define OFF_HBUF (OFF_HS0 + (size_t)TT * BB * HH)          // 2*[B,H] ping-pong
#define SCRATCH_SZ (OFF_HBUF + 2u * (size_t)BB * HH)

__device__ float    g_scratch[SCRATCH_SZ];
__device__ unsigned g_bar[TT];

// ---- lstm_seq smem layout (floats) ----
// Row stride 584 (584%32==8), k-chunk offset 36 (36%32==4): for warp lanes
// (kzp, bt/nt) the 8 distinct addresses per LDS.128 phase land in 8 distinct
// 16B quad-banks -> conflict-free. 16 k-chunks of 32 floats: 16*36=576<=584.
#define HS_STRIDE 584
#define CHUNK_OFF 36
#define PSM_STRIDE 36
#define WSM_FLOATS (16 * HS_STRIDE)
#define HSM_FLOATS (32 * HS_STRIDE)
#define PSM_FLOATS (256 * PSM_STRIDE)
#define SMEM_BYTES ((WSM_FLOATS + HSM_FLOATS + PSM_FLOATS) * sizeof(float))

__device__ __forceinline__ float fast_tanh(float x) {
    float y;
    asm("tanh.approx.f32 %0, %1;" : "=f"(y) : "f"(x));
    return y;
}
__device__ __forceinline__ float fast_sigmoid(float x) {
    return 0.5f * fast_tanh(0.5f * x) + 0.5f;
}

// ---------------------------------------------------------------------------
// Input projection GEMM: Y[m][n] = dot(X(m,:), W[n,:]) + bias[n], N = 2048.
// Logical row m = t*BB + b.
// MODE 0: X row-major [T*B, K].  MODE 1: X is x[B][T][D]; row m -> b*(T*D)+t*D.
// ---------------------------------------------------------------------------
template <int MODE, int K>
__global__ __launch_bounds__(256) void gemm_proj(const float* __restrict__ X,
                                                 const float* __restrict__ W,
                                                 const float* __restrict__ bias,
                                                 float* __restrict__ Y)
{
    __shared__ float Xs[16][64];
    __shared__ float Ws[16][64];

    const int n0  = blockIdx.x * 64;
    const int m0  = blockIdx.y * 64;
    const int tid = threadIdx.x;
    const int tx  = tid & 15;
    const int ty  = tid >> 4;
    const int lrow = tid >> 2;          // 0..63
    const int kp   = (tid & 3) * 4;     // 0,4,8,12

    const float* xrow;
    if (MODE == 0) {
        xrow = X + (size_t)(m0 + lrow) * K;
    } else {
        int m = m0 + lrow;
        int b = m & (BB - 1);
        int t = m >> 5;
        xrow = X + (size_t)b * (TT * DD) + (size_t)t * DD;
    }
    const float* wrow = W + (size_t)(n0 + lrow) * K;

    float acc[4][4];
#pragma unroll
    for (int i = 0; i < 4; i++)
#pragma unroll
        for (int j = 0; j < 4; j++) acc[i][j] = 0.f;

    for (int kk = 0; kk < K; kk += 16) {
        float4 xa = *(const float4*)(xrow + kk + kp);
        float4 wa = *(const float4*)(wrow + kk + kp);
        __syncthreads();
        Xs[kp + 0][lrow] = xa.x; Xs[kp + 1][lrow] = xa.y;
        Xs[kp + 2][lrow] = xa.z; Xs[kp + 3][lrow] = xa.w;
        Ws[kp + 0][lrow] = wa.x; Ws[kp + 1][lrow] = wa.y;
        Ws[kp + 2][lrow] = wa.z; Ws[kp + 3][lrow] = wa.w;
        __syncthreads();
#pragma unroll
        for (int k = 0; k < 16; k++) {
            float4 a = *(const float4*)&Xs[k][ty * 4];
            float4 b = *(const float4*)&Ws[k][tx * 4];
            float av[4] = {a.x, a.y, a.z, a.w};
            float bv[4] = {b.x, b.y, b.z, b.w};
#pragma unroll
            for (int i = 0; i < 4; i++)
#pragma unroll
                for (int j = 0; j < 4; j++) acc[i][j] += av[i] * bv[j];
        }
    }

#pragma unroll
    for (int i = 0; i < 4; i++) {
        int m = m0 + ty * 4 + i;
        float* yr = Y + (size_t)m * G4 + n0 + tx * 4;
#pragma unroll
        for (int j = 0; j < 4; j++)
            yr[j] = acc[i][j] + bias[n0 + tx * 4 + j];
    }
}

// ---------------------------------------------------------------------------
// Persistent recurrent kernel. 128 CTAs; CTA owns h-cols h0..h0+3 (16 gate
// rows).  Per-thread GEMM tile: 8 batches x 4 gate-rows x 32 k.
//   kz = tid>>4 (16 k-chunks of 32),  lane16 = tid&15,
//   bt = lane16>>2 (batches bt+4i, i<8),  nt = lane16&3 (rows nt+4j, j<4;
//   row r = g*4 + hcol -> thread's row nt+4j is gate j, hcol nt).
// acc[i][j] = partial(batch bt+4i, gate j, hcol nt).
// ---------------------------------------------------------------------------
__global__ __launch_bounds__(256) void lstm_seq(const float* __restrict__ Whh,
                                                const float* __restrict__ xp,
                                                float* __restrict__ hbuf,
                                                float* __restrict__ seq,
                                                long st_t, long st_b,
                                                float* __restrict__ hn,
                                                float* __restrict__ cn,
                                                unsigned* __restrict__ bar)
{
    extern __shared__ float sm[];
    float* Wsm = sm;
    float* Hsm = sm + WSM_FLOATS;
    float* Psm = sm + WSM_FLOATS + HSM_FLOATS;

    const int tid = threadIdx.x;
    const int h0  = blockIdx.x * 4;

    // ---- load Whh slice once (chunked layout; coalesced GMEM reads):
    // Wsm row r (0..15) <-> gate r>>2, h-col r&3
#pragma unroll
    for (int it = 0; it < 8; it++) {
        int f  = it * 256 + tid;            // float4 index, 2048 total
        int r  = f >> 7;                    // 128 float4 per row
        int c4 = f & 127;
        const float* grow = Whh + (size_t)((r >> 2) * HH + h0 + (r & 3)) * HH;
        *(float4*)&Wsm[r * HS_STRIDE + (c4 >> 3) * CHUNK_OFF + (c4 & 7) * 4] =
            *(const float4*)(grow + c4 * 4);
    }

    const int kz     = tid >> 4;        // k-chunk (32 k)
    const int lane16 = tid & 15;
    const int bt     = lane16 >> 2;     // batches bt+4i
    const int nt     = lane16 & 3;      // rows nt+4j (gate j, hcol nt)
    const int ub     = tid >> 2;        // update: batch
    const int uj     = tid & 3;         // update: h-col offset

    float cv = 0.f;                     // cell state lives in a register

    for (int t = 0; t < TT; ++t) {
        const float* hprev = hbuf + (size_t)(t & 1) * BH;
        float*       hnext = hbuf + (size_t)((t + 1) & 1) * BH;
        const float* xp_t  = xp + (size_t)t * BB * G4;

        // prefetch gate biases (consumed after the GEMM)
        float xpv[4];
        if (tid < 128) {
#pragma unroll
            for (int g = 0; g < 4; g++)
                xpv[g] = __ldg(xp_t + (size_t)ub * G4 + g * HH + h0 + uj);
        }

        // stage h -> smem (coalesced GMEM, chunked smem layout)
#pragma unroll
        for (int it = 0; it < 16; it++) {
            int f  = it * 256 + tid;        // float4 index, 4096 total
            int b  = f >> 7;
            int c4 = f & 127;
            float4 v = __ldcg((const float4*)(hprev + (size_t)b * HH + c4 * 4));
            *(float4*)&Hsm[b * HS_STRIDE + (c4 >> 3) * CHUNK_OFF + (c4 & 7) * 4] = v;
        }
        __syncthreads();

        // GEMM: 8 batches (bt+4i) x 4 gate-rows (nt+4j) over 32-k chunk
        float acc[8][4];
#pragma unroll
        for (int i = 0; i < 8; i++)
#pragma unroll
            for (int j = 0; j < 4; j++) acc[i][j] = 0.f;

        const float* hbase = &Hsm[bt * HS_STRIDE + kz * CHUNK_OFF];
        const float* wbase = &Wsm[nt * HS_STRIDE + kz * CHUNK_OFF];
#pragma unroll
        for (int kk = 0; kk < 32; kk += 4) {
            float4 wv[4];
#pragma unroll
            for (int j = 0; j < 4; j++)
                wv[j] = *(const float4*)(wbase + j * 4 * HS_STRIDE + kk);
#pragma unroll
            for (int i = 0; i < 8; i++) {
                float4 hv = *(const float4*)(hbase + i * 4 * HS_STRIDE + kk);
#pragma unroll
                for (int j = 0; j < 4; j++)
                    acc[i][j] += hv.x * wv[j].x + hv.y * wv[j].y
                               + hv.z * wv[j].z + hv.w * wv[j].w;
            }
        }

        // partials: Psm row (kz*16 + lane16), elements i*4+j (float4 per i)
        {
            float* pr = &Psm[(kz * 16 + lane16) * PSM_STRIDE];
#pragma unroll
            for (int i = 0; i < 8; i++) {
                float4 v = make_float4(acc[i][0], acc[i][1], acc[i][2], acc[i][3]);
                *(float4*)(pr + i * 4) = v;
            }
        }
        __syncthreads();

        // elementwise update (128 threads: batch ub, h-col h0+uj)
        // partial(batch B, gate g, hcol J): producer lane16' = (B&3)*4+J,
        // element (B>>2)*4+g  -> float4 read per kz gives all 4 gates
        if (tid < 128) {
            float g0 = xpv[0], g1 = xpv[1], g2 = xpv[2], g3 = xpv[3];
            const float* pb = &Psm[((ub & 3) * 4 + uj) * PSM_STRIDE + (ub >> 2) * 4];
#pragma unroll
            for (int z = 0; z < 16; z++) {
                float4 p = *(const float4*)(pb + z * 16 * PSM_STRIDE);
                g0 += p.x; g1 += p.y; g2 += p.z; g3 += p.w;
            }
            float iv = fast_sigmoid(g0);
            float fv = fast_sigmoid(g1);
            float gv = fast_tanh(g2);
            float ov = fast_sigmoid(g3);
            cv = fv * cv + iv * gv;
            float hv = ov * fast_tanh(cv);
            __stcg(hnext + (size_t)ub * HH + h0 + uj, hv);
            seq[(size_t)t * st_t + (size_t)ub * st_b + h0 + uj] = hv;
            if (t == TT - 1 && hn) {
                hn[ub * HH + h0 + uj] = hv;
                cn[ub * HH + h0 + uj] = cv;
            }
        }
        __syncthreads();   // all h stores issued before the fence below

        // grid barrier (cooperative-groups pattern; counters zeroed pre-launch)
        if (tid == 0) {
            unsigned* p = &bar[t];
            unsigned one = 1u;
            asm volatile("fence.acq_rel.gpu;" ::: "memory");
            asm volatile("red.release.gpu.global.add.u32 [%0], %1;"
                         :: "l"(p), "r"(one) : "memory");
            unsigned v;
            do {
                asm volatile("ld.acquire.gpu.global.u32 %0, [%1];"
                             : "=r"(v) : "l"(p) : "memory");
            } while (v < (unsigned)NCTA);
        }
        __syncthreads();
    }
}

// ---------------------------------------------------------------------------
extern "C" void kernel_launch(void* const* d_in, const int* in_sizes, int n_in,
                              void* d_out, int out_size)
{
    const float* x    = (const float*)d_in[0];
    const float* Wih0 = (const float*)d_in[1];
    const float* b0   = (const float*)d_in[2];
    const float* Whh0 = (const float*)d_in[3];
    const float* Wih1 = (const float*)d_in[4];
    const float* b1   = (const float*)d_in[5];
    const float* Whh1 = (const float*)d_in[6];
    float* out = (float*)d_out;

    float* scratch = nullptr;
    unsigned* bar = nullptr;
    cudaGetSymbolAddress((void**)&scratch, g_scratch);
    cudaGetSymbolAddress((void**)&bar, g_bar);
    float* xp   = scratch + OFF_XP;
    float* hs0  = scratch + OFF_HS0;
    float* hbuf = scratch + OFF_HBUF;

    cudaFuncSetAttribute(lstm_seq, cudaFuncAttributeMaxDynamicSharedMemorySize,
                         (int)SMEM_BYTES);

    // outputs: output[B,T,H] ++ h_n[2,B,H] ++ c_n[2,B,H]
    const size_t main_sz = (size_t)BB * TT * HH;            // 16,777,216
    const size_t full_sz = main_sz + 4u * (size_t)BH;       // 16,842,752
    const bool   tail_ok = ((size_t)out_size >= full_sz);
    float* hn_base = tail_ok ? out + main_sz : nullptr;
    float* cn_base = tail_ok ? out + main_sz + 2u * (size_t)BH : nullptr;

    dim3 gproj(G4 / 64, (TT * BB) / 64);  // (32, 512)

    // ---- layer 0 ----
    gemm_proj<1, DD><<<gproj, 256>>>(x, Wih0, b0, xp);
    cudaMemsetAsync(hbuf, 0, 2u * (size_t)BH * sizeof(float));
    cudaMemsetAsync(bar, 0, TT * sizeof(unsigned));
    lstm_seq<<<NCTA, 256, SMEM_BYTES>>>(Whh0, xp, hbuf,
                                        hs0, (long)BH, (long)HH,
                                        hn_base, cn_base, bar);

    // ---- layer 1 ----
    gemm_proj<0, HH><<<gproj, 256>>>(hs0, Wih1, b1, xp);
    cudaMemsetAsync(hbuf, 0, 2u * (size_t)BH * sizeof(float));
    cudaMemsetAsync(bar, 0, TT * sizeof(unsigned));
    lstm_seq<<<NCTA, 256, SMEM_BYTES>>>(Whh1, xp, hbuf,
                                        out, (long)HH, (long)(TT * HH),
                                        hn_base ? hn_base + BH : nullptr,
                                        cn_base ? cn_base + BH : nullptr, bar);
}

// round 15
// speedup vs baseline: 2.9128x; 1.0470x over previous
#include <cuda_runtime.h>
#include <math.h>

// Problem dims (x is batch_first [B, T, D]; B=32, T=1024)
#define BB 32
#define TT 1024
#define DD 256
#define HH 512
#define G4 2048   // 4*H
#define NCTA 128
#define BH (BB * HH)

// ---- scratch inside device globals (no allocations allowed) ----
#define OFF_XP   0u                                        // [T,B,4H]
#define OFF_HS0  (OFF_XP  + (size_t)TT * BB * G4)          // [T,B,H]
#define OFF_HBUF (OFF_HS0 + (size_t)TT * BB * HH)          // 2*[B,H] ping-pong
#define SCRATCH_SZ (OFF_HBUF + 2u * (size_t)BB * HH)

__device__ float    g_scratch[SCRATCH_SZ];
__device__ unsigned g_bar[TT];

// ---- lstm_seq smem layout (floats) ----
// Hsm rows: stride 584 (%32==8), k-chunk offset 36 (%32==4): conflict-free
// LDS.128 phases for the h operand (verified R13/R14).
// Wsm2: W row-pairs, [512 k][8 rp] of 64-bit pairs -> 18 floats per k row.
// Psm: 256 rows x 36 floats (16 x 64-bit pair partials per row).
#define HS_STRIDE 584
#define CHUNK_OFF 36
#define PSM_STRIDE 36
#define W2_STRIDE 18
#define HSM_FLOATS (32 * HS_STRIDE)
#define W2_FLOATS  (512 * W2_STRIDE)
#define PSM_FLOATS (256 * PSM_STRIDE)
#define SMEM_BYTES ((HSM_FLOATS + W2_FLOATS + PSM_FLOATS) * sizeof(float))

__device__ __forceinline__ float fast_tanh(float x) {
    float y;
    asm("tanh.approx.f32 %0, %1;" : "=f"(y) : "f"(x));
    return y;
}
__device__ __forceinline__ float fast_sigmoid(float x) {
    return 0.5f * fast_tanh(0.5f * x) + 0.5f;
}

// ---------------------------------------------------------------------------
// Input projection GEMM: Y[m][n] = dot(X(m,:), W[n,:]) + bias[n], N = 2048.
// Logical row m = t*BB + b.
// MODE 0: X row-major [T*B, K].  MODE 1: X is x[B][T][D]; row m -> b*(T*D)+t*D.
// ---------------------------------------------------------------------------
template <int MODE, int K>
__global__ __launch_bounds__(256) void gemm_proj(const float* __restrict__ X,
                                                 const float* __restrict__ W,
                                                 const float* __restrict__ bias,
                                                 float* __restrict__ Y)
{
    __shared__ float Xs[16][64];
    __shared__ float Ws[16][64];

    const int n0  = blockIdx.x * 64;
    const int m0  = blockIdx.y * 64;
    const int tid = threadIdx.x;
    const int tx  = tid & 15;
    const int ty  = tid >> 4;
    const int lrow = tid >> 2;          // 0..63
    const int kp   = (tid & 3) * 4;     // 0,4,8,12

    const float* xrow;
    if (MODE == 0) {
        xrow = X + (size_t)(m0 + lrow) * K;
    } else {
        int m = m0 + lrow;
        int b = m & (BB - 1);
        int t = m >> 5;
        xrow = X + (size_t)b * (TT * DD) + (size_t)t * DD;
    }
    const float* wrow = W + (size_t)(n0 + lrow) * K;

    float acc[4][4];
#pragma unroll
    for (int i = 0; i < 4; i++)
#pragma unroll
        for (int j = 0; j < 4; j++) acc[i][j] = 0.f;

    for (int kk = 0; kk < K; kk += 16) {
        float4 xa = *(const float4*)(xrow + kk + kp);
        float4 wa = *(const float4*)(wrow + kk + kp);
        __syncthreads();
        Xs[kp + 0][lrow] = xa.x; Xs[kp + 1][lrow] = xa.y;
        Xs[kp + 2][lrow] = xa.z; Xs[kp + 3][lrow] = xa.w;
        Ws[kp + 0][lrow] = wa.x; Ws[kp + 1][lrow] = wa.y;
        Ws[kp + 2][lrow] = wa.z; Ws[kp + 3][lrow] = wa.w;
        __syncthreads();
#pragma unroll
        for (int k = 0; k < 16; k++) {
            float4 a = *(const float4*)&Xs[k][ty * 4];
            float4 b = *(const float4*)&Ws[k][tx * 4];
            float av[4] = {a.x, a.y, a.z, a.w};
            float bv[4] = {b.x, b.y, b.z, b.w};
#pragma unroll
            for (int i = 0; i < 4; i++)
#pragma unroll
                for (int j = 0; j < 4; j++) acc[i][j] += av[i] * bv[j];
        }
    }

#pragma unroll
    for (int i = 0; i < 4; i++) {
        int m = m0 + ty * 4 + i;
        float* yr = Y + (size_t)m * G4 + n0 + tx * 4;
#pragma unroll
        for (int j = 0; j < 4; j++)
            yr[j] = acc[i][j] + bias[n0 + tx * 4 + j];
    }
}

// ---------------------------------------------------------------------------
// Persistent recurrent kernel with packed f32x2 math.
// 128 CTAs; CTA owns h-cols h0..h0+3 -> 16 gate rows r = g*4 + hcol.
// Row-pairs rp (0..7) hold rows (2rp, 2rp+1): rp = 2g + (hcol>>1), s = hcol&1.
// Thread (kz = tid>>4, lane16 = tid&15 -> bt = lane16>>2, nt = lane16&3):
//   batches {bt+4i, i<8} x row-pairs {nt, nt+4} over 32-k chunk.
//   acc64[i][jp] = f32x2 pair partial for (batch bt+4i, rows 2*(nt+4jp)+{0,1}).
// ---------------------------------------------------------------------------
__global__ __launch_bounds__(256) void lstm_seq(const float* __restrict__ Whh,
                                                const float* __restrict__ xp,
                                                float* __restrict__ hbuf,
                                                float* __restrict__ seq,
                                                long st_t, long st_b,
                                                float* __restrict__ hn,
                                                float* __restrict__ cn,
                                                unsigned* __restrict__ bar)
{
    extern __shared__ float sm[];
    float* Hsm  = sm;
    float* Wsm2 = sm + HSM_FLOATS;
    float* Psm  = sm + HSM_FLOATS + W2_FLOATS;

    const int tid = threadIdx.x;
    const int h0  = blockIdx.x * 4;

    // ---- build W row-pair table once (ST conflicts here are irrelevant):
    // Wsm2[k*18 + rp*2 + s] = Whh[((r>>2)*H + h0 + (r&3))*H + k], r = 2rp+s
#pragma unroll
    for (int it = 0; it < 8; it++) {
        int f4 = it * 256 + tid;            // 0..2047
        int r  = f4 >> 7;                   // gate-row 0..15
        int c4 = f4 & 127;                  // k/4
        const float* grow = Whh + (size_t)((r >> 2) * HH + h0 + (r & 3)) * HH;
        float4 v = *(const float4*)(grow + c4 * 4);
        float* dst = &Wsm2[(r >> 1) * 2 + (r & 1)];
        dst[(c4 * 4 + 0) * W2_STRIDE] = v.x;
        dst[(c4 * 4 + 1) * W2_STRIDE] = v.y;
        dst[(c4 * 4 + 2) * W2_STRIDE] = v.z;
        dst[(c4 * 4 + 3) * W2_STRIDE] = v.w;
    }

    const int kz     = tid >> 4;        // k-chunk (32 k)
    const int lane16 = tid & 15;
    const int bt     = lane16 >> 2;     // batches bt+4i
    const int nt     = lane16 & 3;      // row-pairs nt, nt+4
    const int ub     = tid >> 2;        // update: batch
    const int uj     = tid & 3;         // update: h-col offset

    float cv = 0.f;                     // cell state lives in a register

    for (int t = 0; t < TT; ++t) {
        const float* hprev = hbuf + (size_t)(t & 1) * BH;
        float*       hnext = hbuf + (size_t)((t + 1) & 1) * BH;
        const float* xp_t  = xp + (size_t)t * BB * G4;

        // prefetch gate biases (consumed after the GEMM)
        float xpv[4];
        if (tid < 128) {
#pragma unroll
            for (int g = 0; g < 4; g++)
                xpv[g] = __ldg(xp_t + (size_t)ub * G4 + g * HH + h0 + uj);
        }

        // stage h -> smem (coalesced GMEM, chunked smem layout; as R14)
#pragma unroll
        for (int it = 0; it < 16; it++) {
            int f  = it * 256 + tid;        // float4 index, 4096 total
            int b  = f >> 7;
            int c4 = f & 127;
            float4 v = __ldcg((const float4*)(hprev + (size_t)b * HH + c4 * 4));
            *(float4*)&Hsm[b * HS_STRIDE + (c4 >> 3) * CHUNK_OFF + (c4 & 7) * 4] = v;
        }
        __syncthreads();

        // GEMM: 8 batches x 2 row-pairs x 32 k, packed f32x2
        unsigned long long acc64[8][2];
#pragma unroll
        for (int i = 0; i < 8; i++) { acc64[i][0] = 0ull; acc64[i][1] = 0ull; }

        const float* hbase = &Hsm[bt * HS_STRIDE + kz * CHUNK_OFF];
        const float* wbase = &Wsm2[(size_t)(kz * 32) * W2_STRIDE + nt * 2];
#pragma unroll
        for (int kk = 0; kk < 32; kk += 4) {
            float4 hv[8];
#pragma unroll
            for (int i = 0; i < 8; i++)
                hv[i] = *(const float4*)(hbase + i * 4 * HS_STRIDE + kk);
#pragma unroll
            for (int m = 0; m < 4; m++) {
                const float* wk = wbase + (kk + m) * W2_STRIDE;
                unsigned long long w0 = *(const unsigned long long*)(wk);
                unsigned long long w1 = *(const unsigned long long*)(wk + 8);
#pragma unroll
                for (int i = 0; i < 8; i++) {
                    float h = (m == 0) ? hv[i].x : (m == 1) ? hv[i].y
                              : (m == 2) ? hv[i].z : hv[i].w;
                    unsigned long long hp;
                    asm("mov.b64 %0, {%1, %1};" : "=l"(hp) : "f"(h));
                    asm("fma.rn.f32x2 %0, %1, %2, %3;"
                        : "=l"(acc64[i][0]) : "l"(hp), "l"(w0), "l"(acc64[i][0]));
                    asm("fma.rn.f32x2 %0, %1, %2, %3;"
                        : "=l"(acc64[i][1]) : "l"(hp), "l"(w1), "l"(acc64[i][1]));
                }
            }
        }

        // partials: Psm row (kz*16+lane16), 64-bit elems: (i, jp) at float 4i+2jp
        {
            float* pr = &Psm[(kz * 16 + lane16) * PSM_STRIDE];
#pragma unroll
            for (int i = 0; i < 8; i++) {
                ulonglong2 v; v.x = acc64[i][0]; v.y = acc64[i][1];
                *(ulonglong2*)(pr + i * 4) = v;
            }
        }
        __syncthreads();

        // elementwise update (128 threads: batch ub, h-col h0+uj)
        // gate g of (B,uj): rp = 2g + (uj>>1), s = uj&1; producer lane16' =
        // (B&3)*4 + (rp&3), elem float = 4*(B>>2) + 2*(rp>>2) + s
        if (tid < 128) {
            const int a = uj >> 1;
            const int s = uj & 1;
            float g0 = xpv[0], g1 = xpv[1], g2 = xpv[2], g3 = xpv[3];
            const float* pb = Psm + ((ub & 3) * 4) * PSM_STRIDE + 4 * (ub >> 2) + s;
#pragma unroll
            for (int z = 0; z < 16; z++) {
                const float* pz = pb + z * 16 * PSM_STRIDE;
                g0 += pz[a * PSM_STRIDE];                 // rp=a    (g0, jp0)
                g1 += pz[(2 + a) * PSM_STRIDE];           // rp=2+a  (g1, jp0)
                g2 += pz[a * PSM_STRIDE + 2];             // rp=4+a  (g2, jp1)
                g3 += pz[(2 + a) * PSM_STRIDE + 2];       // rp=6+a  (g3, jp1)
            }
            float iv = fast_sigmoid(g0);
            float fv = fast_sigmoid(g1);
            float gv = fast_tanh(g2);
            float ov = fast_sigmoid(g3);
            cv = fv * cv + iv * gv;
            float hv = ov * fast_tanh(cv);
            __stcg(hnext + (size_t)ub * HH + h0 + uj, hv);
            seq[(size_t)t * st_t + (size_t)ub * st_b + h0 + uj] = hv;
            if (t == TT - 1 && hn) {
                hn[ub * HH + h0 + uj] = hv;
                cn[ub * HH + h0 + uj] = cv;
            }
        }
        __syncthreads();   // all h stores issued before the fence below

        // grid barrier (cooperative-groups pattern; counters zeroed pre-launch)
        if (tid == 0) {
            unsigned* p = &bar[t];
            unsigned one = 1u;
            asm volatile("fence.acq_rel.gpu;" ::: "memory");
            asm volatile("red.release.gpu.global.add.u32 [%0], %1;"
                         :: "l"(p), "r"(one) : "memory");
            unsigned v;
            do {
                asm volatile("ld.acquire.gpu.global.u32 %0, [%1];"
                             : "=r"(v) : "l"(p) : "memory");
            } while (v < (unsigned)NCTA);
        }
        __syncthreads();
    }
}

// ---------------------------------------------------------------------------
extern "C" void kernel_launch(void* const* d_in, const int* in_sizes, int n_in,
                              void* d_out, int out_size)
{
    const float* x    = (const float*)d_in[0];
    const float* Wih0 = (const float*)d_in[1];
    const float* b0   = (const float*)d_in[2];
    const float* Whh0 = (const float*)d_in[3];
    const float* Wih1 = (const float*)d_in[4];
    const float* b1   = (const float*)d_in[5];
    const float* Whh1 = (const float*)d_in[6];
    float* out = (float*)d_out;

    float* scratch = nullptr;
    unsigned* bar = nullptr;
    cudaGetSymbolAddress((void**)&scratch, g_scratch);
    cudaGetSymbolAddress((void**)&bar, g_bar);
    float* xp   = scratch + OFF_XP;
    float* hs0  = scratch + OFF_HS0;
    float* hbuf = scratch + OFF_HBUF;

    cudaFuncSetAttribute(lstm_seq, cudaFuncAttributeMaxDynamicSharedMemorySize,
                         (int)SMEM_BYTES);

    // outputs: output[B,T,H] ++ h_n[2,B,H] ++ c_n[2,B,H]
    const size_t main_sz = (size_t)BB * TT * HH;            // 16,777,216
    const size_t full_sz = main_sz + 4u * (size_t)BH;       // 16,842,752
    const bool   tail_ok = ((size_t)out_size >= full_sz);
    float* hn_base = tail_ok ? out + main_sz : nullptr;
    float* cn_base = tail_ok ? out + main_sz + 2u * (size_t)BH : nullptr;

    dim3 gproj(G4 / 64, (TT * BB) / 64);  // (32, 512)

    // ---- layer 0 ----
    gemm_proj<1, DD><<<gproj, 256>>>(x, Wih0, b0, xp);
    cudaMemsetAsync(hbuf, 0, 2u * (size_t)BH * sizeof(float));
    cudaMemsetAsync(bar, 0, TT * sizeof(unsigned));
    lstm_seq<<<NCTA, 256, SMEM_BYTES>>>(Whh0, xp, hbuf,
                                        hs0, (long)BH, (long)HH,
                                        hn_base, cn_base, bar);

    // ---- layer 1 ----
    gemm_proj<0, HH><<<gproj, 256>>>(hs0, Wih1, b1, xp);
    cudaMemsetAsync(hbuf, 0, 2u * (size_t)BH * sizeof(float));
    cudaMemsetAsync(bar, 0, TT * sizeof(unsigned));
    lstm_seq<<<NCTA, 256, SMEM_BYTES>>>(Whh1, xp, hbuf,
                                        out, (long)HH, (long)(TT * HH),
                                        hn_base ? hn_base + BH : nullptr,
                                        cn_base ? cn_base + BH : nullptr, bar);
}